// round 4
// baseline (speedup 1.0000x reference)
#include <cuda_runtime.h>

#define BB 32
#define CC 512
#define C8 64
#define NPIX 4096
#define NT 128
#define CT 64
#define CTILES (CC/CT)           // 8
#define NITEMS (BB * (NPIX/NT))  // 1024

typedef unsigned long long u64t;

__device__ __forceinline__ u64t pack2(float lo, float hi) {
    u64t r; asm("mov.b64 %0, {%1, %2};" : "=l"(r) : "f"(lo), "f"(hi)); return r;
}
__device__ __forceinline__ u64t fma2(u64t a, u64t b, u64t c) {
    u64t d; asm("fma.rn.f32x2 %0, %1, %2, %3;" : "=l"(d) : "l"(a), "l"(b), "l"(c)); return d;
}
__device__ __forceinline__ u64t add2(u64t a, u64t b) {
    u64t d; asm("add.rn.f32x2 %0, %1, %2;" : "=l"(d) : "l"(a), "l"(b)); return d;
}
__device__ __forceinline__ void unpack2(u64t v, float& lo, float& hi) {
    asm("mov.b64 {%0, %1}, %2;" : "=f"(lo), "=f"(hi) : "l"(v));
}

// Scratch (device globals — no allocation allowed)
__device__ float g_logits[BB*C8*C8];
__device__ float g_xsum[BB*CC];
__device__ float g_wq2[CC*128];   // splatted: [c][2*o..2*o+1] = wq[o][c]
__device__ float g_wk2[CC*128];
__device__ unsigned g_ctr;

// -------------------------------------------------------------------------
__global__ void prep_kernel(const float* __restrict__ wq,
                            const float* __restrict__ wk) {
    int t = blockIdx.x * blockDim.x + threadIdx.x;
    int S = gridDim.x * blockDim.x;
    if (t == 0) g_ctr = 0;
    for (int i = t; i < BB*C8*C8; i += S) g_logits[i] = 0.f;
    for (int i = t; i < BB*CC;    i += S) g_xsum[i]   = 0.f;
    for (int i = t; i < CC*C8;    i += S) {
        int c = i >> 6, o = i & 63;
        float vq = wq[o*CC + c], vk = wk[o*CC + c];
        g_wq2[c*128 + 2*o]     = vq;
        g_wq2[c*128 + 2*o + 1] = vq;
        g_wk2[c*128 + 2*o]     = vk;
        g_wk2[c*128 + 2*o + 1] = vk;
    }
}

// -------------------------------------------------------------------------
// Persistent work-stealing kernel. Item = (batch, 128-px n-tile).
// Inner loop is pure: 6x LDS.128 + 32x FFMA2 per c-step (no operand MOVs —
// weights pre-splatted in smem so every LDS.128 yields ready f32x2 pairs).
//
// smem floats: x_s [0,8192) | wq2_s [8192,16384) | wk2_s [16384,24576)
// phase2 alias: q_s[64][130] @0 | k_s[64][130] @8320
// -------------------------------------------------------------------------
#define SMEM_FLOATS 24576
#define SMEM_BYTES  (SMEM_FLOATS * 4)

__global__ void __launch_bounds__(256, 2)
logits_kernel(const float* __restrict__ x,
              const float* __restrict__ bq,
              const float* __restrict__ bk)
{
    extern __shared__ float sm[];
    float* x_s   = sm;           // [64][128]
    float* wq2_s = sm + 8192;    // [64][128] splatted
    float* wk2_s = sm + 16384;   // [64][128] splatted
    float* q_s   = sm;           // [64][130] (phase 2 alias)
    float* k_s   = sm + 8320;    // [64][130]
    __shared__ unsigned item_s;

    const int tid = threadIdx.x;
    const int tx = tid & 15;
    const int ty = tid >> 4;
    const int o0 = ty * 4;     // 4 output rows per thread
    const int n0 = tx * 8;     // 8 pixels per thread (phase 1)
    const int p0 = tx * 4;     // 4 logit cols per thread (phase 2)
    const int c_local = tid >> 2;
    const int quad    = tid & 3;

    u64t bq2[4], bk2[4];
    #pragma unroll
    for (int i = 0; i < 4; i++) {
        float vq = bq[o0+i], vk = bk[o0+i];
        bq2[i] = pack2(vq, vq);
        bk2[i] = pack2(vk, vk);
    }

    while (true) {
        if (tid == 0) item_s = atomicAdd(&g_ctr, 1u);
        __syncthreads();
        const unsigned item = item_s;
        if (item >= NITEMS) break;
        const int b = item >> 5;
        const int n_base = (item & 31) * NT;

        u64t qa[4][4], ka[4][4];
        #pragma unroll
        for (int i = 0; i < 4; i++)
            #pragma unroll
            for (int j = 0; j < 4; j++) { qa[i][j] = 0ull; ka[i][j] = 0ull; }

        for (int ct = 0; ct < CTILES; ++ct) {
            __syncthreads();  // prior-phase smem reads complete

            // --- load x tile [64c][128n], channel partial sums ---
            const float* xg = x + ((size_t)b*CC + (size_t)(ct*CT + c_local))*NPIX + n_base;
            float psum = 0.f;
            #pragma unroll
            for (int k2 = 0; k2 < 8; ++k2) {
                int noff = quad*4 + k2*16;
                float4 v = *(const float4*)(xg + noff);
                *(float4*)&x_s[c_local*NT + noff] = v;
                psum += v.x + v.y + v.z + v.w;
            }
            psum += __shfl_xor_sync(0xffffffffu, psum, 1);
            psum += __shfl_xor_sync(0xffffffffu, psum, 2);
            if (quad == 0) atomicAdd(&g_xsum[b*CC + ct*CT + c_local], psum);

            // --- copy splatted weight tiles [64c][128] from L2 ---
            {
                const float4* srcq = (const float4*)&g_wq2[(ct*CT)*128];
                const float4* srck = (const float4*)&g_wk2[(ct*CT)*128];
                float4* dq = (float4*)wq2_s;
                float4* dk = (float4*)wk2_s;
                #pragma unroll
                for (int i = 0; i < 8; ++i) {
                    dq[tid + i*256] = srcq[tid + i*256];
                    dk[tid + i*256] = srck[tid + i*256];
                }
            }
            __syncthreads();

            // --- packed projection: 6 LDS.128 + 32 FFMA2 per c-step ---
            #pragma unroll 8
            for (int c = 0; c < CT; ++c) {
                ulonglong2 wqA = *(const ulonglong2*)&wq2_s[c*128 + 2*o0];
                ulonglong2 wqB = *(const ulonglong2*)&wq2_s[c*128 + 2*o0 + 4];
                ulonglong2 wkA = *(const ulonglong2*)&wk2_s[c*128 + 2*o0];
                ulonglong2 wkB = *(const ulonglong2*)&wk2_s[c*128 + 2*o0 + 4];
                ulonglong2 xa  = *(const ulonglong2*)&x_s[c*NT + n0];
                ulonglong2 xb  = *(const ulonglong2*)&x_s[c*NT + n0 + 4];
                u64t wq2v[4] = {wqA.x, wqA.y, wqB.x, wqB.y};
                u64t wk2v[4] = {wkA.x, wkA.y, wkB.x, wkB.y};
                u64t x2[4]   = {xa.x, xa.y, xb.x, xb.y};
                #pragma unroll
                for (int i = 0; i < 4; i++)
                    #pragma unroll
                    for (int j = 0; j < 4; j++) {
                        qa[i][j] = fma2(wq2v[i], x2[j], qa[i][j]);
                        ka[i][j] = fma2(wk2v[i], x2[j], ka[i][j]);
                    }
            }
        }
        __syncthreads();

        // --- q,k (+bias) -> smem [o][n] stride 130, packed pairs along n ---
        #pragma unroll
        for (int i = 0; i < 4; i++)
            #pragma unroll
            for (int j = 0; j < 4; j++) {
                *(u64t*)&q_s[(o0+i)*130 + n0 + 2*j] = add2(qa[i][j], bq2[i]);
                *(u64t*)&k_s[(o0+i)*130 + n0 + 2*j] = add2(ka[i][j], bk2[i]);
            }
        __syncthreads();

        // --- logits += q @ k^T, packed along reduction dim ---
        u64t lacc[4][4];
        #pragma unroll
        for (int i = 0; i < 4; i++)
            #pragma unroll
            for (int j = 0; j < 4; j++) lacc[i][j] = 0ull;

        #pragma unroll 4
        for (int np = 0; np < NT/2; ++np) {
            u64t q2[4], k2[4];
            #pragma unroll
            for (int i = 0; i < 4; i++) q2[i] = *(const u64t*)&q_s[(o0+i)*130 + 2*np];
            #pragma unroll
            for (int j = 0; j < 4; j++) k2[j] = *(const u64t*)&k_s[(p0+j)*130 + 2*np];
            #pragma unroll
            for (int i = 0; i < 4; i++)
                #pragma unroll
                for (int j = 0; j < 4; j++)
                    lacc[i][j] = fma2(q2[i], k2[j], lacc[i][j]);
        }

        float* Lg = g_logits + b*C8*C8;
        #pragma unroll
        for (int i = 0; i < 4; i++)
            #pragma unroll
            for (int j = 0; j < 4; j++) {
                float lo, hi; unpack2(lacc[i][j], lo, hi);
                atomicAdd(&Lg[(o0+i)*C8 + p0 + j], lo + hi);
            }
        __syncthreads();  // protect q_s/k_s vs next item's smem writes
    }
}

// -------------------------------------------------------------------------
__global__ void finalize_kernel(const float* __restrict__ wv,
                                const float* __restrict__ bv,
                                float* __restrict__ out)
{
    __shared__ float vmean_s[C8];
    __shared__ float attn_s[C8][C8 + 1];
    const int b = blockIdx.x;
    const int t = threadIdx.x;  // 0..63

    const float* xs = g_xsum + b*CC;
    float acc = 0.f;
    for (int c = 0; c < CC; ++c) acc += wv[t*CC + c] * xs[c];
    vmean_s[t] = acc * (1.f / NPIX) + bv[t];

    const float* Lg = g_logits + b*C8*C8;
    float col[C8];
    float m = -1e30f;
    #pragma unroll
    for (int o = 0; o < C8; ++o) { col[o] = Lg[o*C8 + t]; m = fmaxf(m, col[o]); }
    float s = 0.f;
    #pragma unroll
    for (int o = 0; o < C8; ++o) { col[o] = expf(col[o] - m); s += col[o]; }
    float inv = 1.f / s;
    #pragma unroll
    for (int o = 0; o < C8; ++o) attn_s[o][t] = col[o] * inv;
    __syncthreads();

    float r = 0.f;
    #pragma unroll
    for (int p = 0; p < C8; ++p) r += attn_s[t][p] * vmean_s[p];
    out[b*C8 + t] = r;
}

// -------------------------------------------------------------------------
extern "C" void kernel_launch(void* const* d_in, const int* in_sizes, int n_in,
                              void* d_out, int out_size) {
    const float* x  = (const float*)d_in[0];
    const float* wq = (const float*)d_in[1];
    const float* bq = (const float*)d_in[2];
    const float* wk = (const float*)d_in[3];
    const float* bk = (const float*)d_in[4];
    const float* wv = (const float*)d_in[5];
    const float* bv = (const float*)d_in[6];
    float* out = (float*)d_out;

    cudaFuncSetAttribute(logits_kernel,
                         cudaFuncAttributeMaxDynamicSharedMemorySize, SMEM_BYTES);

    prep_kernel<<<128, 256>>>(wq, wk);
    logits_kernel<<<296, 256, SMEM_BYTES>>>(x, bq, bk);
    finalize_kernel<<<BB, C8>>>(wv, bv, out);
}

// round 7
// speedup vs baseline: 1.0462x; 1.0462x over previous
#include <cuda_runtime.h>

#define BB 32
#define CC 512
#define C8 64
#define NPIX 4096
#define NT 128
#define CT 64
#define CTILES 8
#define NITEMS (BB*(NPIX/NT))   // 1024

#define ROWB 144                 // padded row stride (bytes): conflict-free ldmatrix
#define PLANE (128*ROWB)         // 18432 B per bf16 plane tile
#define SM_W 0                   // 3 planes of W   [p][m=128][k=64(+pad)]
#define SM_X (3*PLANE)           // 3 planes of X   [p][n=128][k=64(+pad)]
#define SMEM_BYTES (6*PLANE)     // 110592

typedef unsigned u32;
typedef unsigned long long u64t;
typedef unsigned short u16t;

// ---------------- helpers ----------------
__device__ __forceinline__ u32 smem_u32(const void* p) {
    u32 a; asm("{ .reg .u64 t; cvta.to.shared.u64 t, %1; cvt.u32.u64 %0, t; }" : "=r"(a) : "l"(p));
    return a;
}
// exact 3-way bf16 truncation split: f = h0 + h1 + h2 + O(2^-24 |f|)
__device__ __forceinline__ void split3(float f, u32& h0, u32& h1, u32& h2) {
    u32 u = __float_as_uint(f);
    h0 = u & 0xFFFF0000u;
    float r1 = f - __uint_as_float(h0);
    h1 = __float_as_uint(r1) & 0xFFFF0000u;
    float r2 = r1 - __uint_as_float(h1);
    h2 = __float_as_uint(r2) & 0xFFFF0000u;
}
__device__ __forceinline__ u64t pack2f(float lo, float hi) {
    u64t r; asm("mov.b64 %0, {%1, %2};" : "=l"(r) : "f"(lo), "f"(hi)); return r;
}
__device__ __forceinline__ u64t fma2(u64t a, u64t b, u64t c) {
    u64t d; asm("fma.rn.f32x2 %0, %1, %2, %3;" : "=l"(d) : "l"(a), "l"(b), "l"(c)); return d;
}
__device__ __forceinline__ void unpack2(u64t v, float& lo, float& hi) {
    asm("mov.b64 {%0, %1}, %2;" : "=f"(lo), "=f"(hi) : "l"(v));
}
__device__ __forceinline__ void ldsm4(u32* r, u32 addr) {
    asm volatile("ldmatrix.sync.aligned.m8n8.x4.shared.b16 {%0,%1,%2,%3}, [%4];"
        : "=r"(r[0]), "=r"(r[1]), "=r"(r[2]), "=r"(r[3]) : "r"(addr));
}
__device__ __forceinline__ void ldsm2(u32* r, u32 addr) {
    asm volatile("ldmatrix.sync.aligned.m8n8.x2.shared.b16 {%0,%1}, [%2];"
        : "=r"(r[0]), "=r"(r[1]) : "r"(addr));
}
__device__ __forceinline__ void mma_bf16(float* d, const u32* a, const u32* b) {
    asm volatile("mma.sync.aligned.m16n8k16.row.col.f32.bf16.bf16.f32 "
        "{%0,%1,%2,%3}, {%4,%5,%6,%7}, {%8,%9}, {%0,%1,%2,%3};"
        : "+f"(d[0]), "+f"(d[1]), "+f"(d[2]), "+f"(d[3])
        : "r"(a[0]), "r"(a[1]), "r"(a[2]), "r"(a[3]), "r"(b[0]), "r"(b[1]));
}
__device__ __forceinline__ uint4 pack4h(const u32* h) {  // 8 bf16(hi-16) -> uint4
    return make_uint4(__byte_perm(h[0],h[1],0x7632), __byte_perm(h[2],h[3],0x7632),
                      __byte_perm(h[4],h[5],0x7632), __byte_perm(h[6],h[7],0x7632));
}

// ---------------- globals (no allocation allowed) ----------------
__device__ float g_logits[BB*C8*C8];
__device__ float g_xsum[BB*CC];
__device__ uint4 g_w4[8*3456];   // per ct: [p][m=128][72 halves] bf16, padded rows
__device__ unsigned g_ctr;

// -------------------------------------------------------------------------
__global__ void prep_kernel(const float* __restrict__ wq,
                            const float* __restrict__ wk) {
    int t = blockIdx.x * blockDim.x + threadIdx.x;
    int S = gridDim.x * blockDim.x;
    if (t == 0) g_ctr = 0;
    for (int i = t; i < BB*C8*C8; i += S) g_logits[i] = 0.f;
    for (int i = t; i < BB*CC;    i += S) g_xsum[i]   = 0.f;
    u16t* wh = (u16t*)g_w4;
    const int total = 8*3*128*72;
    for (int i = t; i < total; i += S) {
        int kk = i % 72;
        int m  = (i / 72) & 127;
        int p  = (i / (72*128)) % 3;
        int ct = i / (72*128*3);
        u16t hv = 0;
        if (kk < 64) {
            int c = ct*64 + kk;
            float v = (m < 64) ? wq[m*CC + c] : wk[(m-64)*CC + c];
            u32 h0, h1, h2; split3(v, h0, h1, h2);
            u32 sel = (p == 0) ? h0 : ((p == 1) ? h1 : h2);
            hv = (u16t)(sel >> 16);
        }
        wh[i] = hv;
    }
}

// -------------------------------------------------------------------------
// Persistent kernel. Item = (batch, 128-px tile).
//  per k-chunk: copy W bf16 planes (L2), convert x->3 bf16 X planes [n][k],
//  ldmatrix + mma.sync bf16 (6 split combos, fp32 accum in registers).
//  Then q,k -> smem, FFMA2 logits, atomic flush.
// -------------------------------------------------------------------------
__global__ void __launch_bounds__(256, 2)
qk_kernel(const float* __restrict__ x,
          const float* __restrict__ bq,
          const float* __restrict__ bk)
{
    extern __shared__ char smem[];
    const u32 smem_base = smem_u32(smem);
    float* q_s = (float*)smem;           // [64][130] fp32 (post-mma alias)
    float* k_s = (float*)smem + 8320;
    __shared__ unsigned item_s;

    const int tid  = threadIdx.x;
    const int lane = tid & 31;
    const int wid  = tid >> 5;
    const int wm = wid & 3;              // M slice: m in [32*wm, 32*wm+32)
    const int wn = wid >> 2;             // N slice: n in [64*wn, 64*wn+64)
    const int mbase = wm*32, nbase = wn*64;

    // ldmatrix per-lane byte offsets (invariant)
    u32 offA[2], offB[8];
    #pragma unroll
    for (int mt = 0; mt < 2; mt++)
        offA[mt] = (u32)((mbase + mt*16 + (lane & 15))*ROWB + (lane >> 4)*16);
    #pragma unroll
    for (int nt = 0; nt < 8; nt++)
        offB[nt] = (u32)((nbase + nt*8 + (lane & 7))*ROWB + ((lane >> 3) & 1)*16);

    // bias for the q/k rows this thread writes
    const float* bsrc = (wm < 2) ? bq : bk;
    const int rq = lane >> 2;
    float bias0[2], bias1[2];
    #pragma unroll
    for (int mt = 0; mt < 2; mt++) {
        int r = (mbase & 63) + mt*16 + rq;
        bias0[mt] = bsrc[r];
        bias1[mt] = bsrc[r + 8];
    }

    const int cw = wid * 8;              // convert: 8 channels owned by this warp
    const int tx = tid & 15, ty = tid >> 4;
    const int o0 = ty * 4, p0 = tx * 4;  // logits tile

    while (true) {
        if (tid == 0) item_s = atomicAdd(&g_ctr, 1u);
        __syncthreads();
        const unsigned item = item_s;
        if (item >= NITEMS) break;
        const int b = item >> 5;
        const int n0g = (int)(item & 31) * NT;

        float acc[2][8][4];
        #pragma unroll
        for (int mt = 0; mt < 2; mt++)
            #pragma unroll
            for (int nt = 0; nt < 8; nt++)
                #pragma unroll
                for (int r = 0; r < 4; r++) acc[mt][nt][r] = 0.f;

        for (int ct = 0; ct < CTILES; ++ct) {
            __syncthreads();  // prior-phase smem reads complete

            // ---- copy W bf16 planes for this chunk (L2-resident) ----
            {
                const uint4* src = g_w4 + ct*3456;
                uint4* dW = (uint4*)(smem + SM_W);
                for (int i = tid; i < 3456; i += 256) dW[i] = src[i];
            }

            // ---- convert x[64c x 128n] -> 3 bf16 planes [n][k=c] ----
            float csum[8];
            #pragma unroll
            for (int j = 0; j < 8; j++) csum[j] = 0.f;
            const float* xb = x + ((size_t)b*CC + (size_t)(ct*CT + cw))*NPIX + n0g;
            #pragma unroll
            for (int ni = 0; ni < 4; ni++) {
                const int n = ni*32 + lane;
                u32 h0[8], h1[8], h2[8];
                #pragma unroll
                for (int j = 0; j < 8; j++) {
                    float v = xb[(size_t)j*NPIX + n];
                    split3(v, h0[j], h1[j], h2[j]);
                    csum[j] += v;
                }
                char* dst = smem + SM_X + n*ROWB + cw*2;
                *(uint4*)(dst)           = pack4h(h0);
                *(uint4*)(dst + PLANE)   = pack4h(h1);
                *(uint4*)(dst + 2*PLANE) = pack4h(h2);
            }
            #pragma unroll
            for (int j = 0; j < 8; j++) {
                float s = csum[j];
                s += __shfl_xor_sync(0xffffffffu, s, 16);
                s += __shfl_xor_sync(0xffffffffu, s, 8);
                s += __shfl_xor_sync(0xffffffffu, s, 4);
                s += __shfl_xor_sync(0xffffffffu, s, 2);
                s += __shfl_xor_sync(0xffffffffu, s, 1);
                if (lane == 0) atomicAdd(&g_xsum[b*CC + ct*CT + cw + j], s);
            }
            __syncthreads();

            // ---- tensor phase: 6 combos x 4 k-steps x (2m x 8n) mma ----
            const int pa[6] = {0,0,1,1,0,2};
            const int pb[6] = {0,1,0,1,2,0};
            #pragma unroll
            for (int cb = 0; cb < 6; cb++) {
                const u32 baseA = smem_base + SM_W + pa[cb]*PLANE;
                const u32 baseB = smem_base + SM_X + pb[cb]*PLANE;
                #pragma unroll
                for (int ks = 0; ks < 4; ks++) {
                    u32 a[2][4];
                    ldsm4(a[0], baseA + offA[0] + ks*32);
                    ldsm4(a[1], baseA + offA[1] + ks*32);
                    u32 bf[8][2];
                    #pragma unroll
                    for (int nt = 0; nt < 8; nt++)
                        ldsm2(bf[nt], baseB + offB[nt] + ks*32);
                    #pragma unroll
                    for (int mt = 0; mt < 2; mt++)
                        #pragma unroll
                        for (int nt = 0; nt < 8; nt++)
                            mma_bf16(acc[mt][nt], a[mt], bf[nt]);
                }
            }
        }
        __syncthreads();  // all mma smem reads done; alias q_s/k_s

        // ---- q,k (+bias) -> smem [row][n] stride 130 ----
        {
            float* dst = (wm < 2) ? q_s : k_s;
            #pragma unroll
            for (int mt = 0; mt < 2; mt++) {
                const int r0 = (mbase & 63) + mt*16 + rq;
                #pragma unroll
                for (int nt = 0; nt < 8; nt++) {
                    const int col = nbase + nt*8 + (lane & 3)*2;
                    *(u64t*)&dst[r0*130 + col] =
                        pack2f(acc[mt][nt][0] + bias0[mt], acc[mt][nt][1] + bias0[mt]);
                    *(u64t*)&dst[(r0+8)*130 + col] =
                        pack2f(acc[mt][nt][2] + bias1[mt], acc[mt][nt][3] + bias1[mt]);
                }
            }
        }
        __syncthreads();

        // ---- logits += q @ k^T (packed f32x2 along n) ----
        u64t lacc[4][4];
        #pragma unroll
        for (int i = 0; i < 4; i++)
            #pragma unroll
            for (int j = 0; j < 4; j++) lacc[i][j] = 0ull;

        #pragma unroll 4
        for (int np = 0; np < NT/2; ++np) {
            u64t q2[4], k2[4];
            #pragma unroll
            for (int i = 0; i < 4; i++) q2[i] = *(const u64t*)&q_s[(o0+i)*130 + 2*np];
            #pragma unroll
            for (int j = 0; j < 4; j++) k2[j] = *(const u64t*)&k_s[(p0+j)*130 + 2*np];
            #pragma unroll
            for (int i = 0; i < 4; i++)
                #pragma unroll
                for (int j = 0; j < 4; j++)
                    lacc[i][j] = fma2(q2[i], k2[j], lacc[i][j]);
        }
        float* Lg = g_logits + b*C8*C8;
        #pragma unroll
        for (int i = 0; i < 4; i++)
            #pragma unroll
            for (int j = 0; j < 4; j++) {
                float lo, hi; unpack2(lacc[i][j], lo, hi);
                atomicAdd(&Lg[(o0+i)*C8 + p0 + j], lo + hi);
            }
        // loop-top __syncthreads guards smem reuse for next item
    }
}

// -------------------------------------------------------------------------
__global__ void finalize_kernel(const float* __restrict__ wv,
                                const float* __restrict__ bv,
                                float* __restrict__ out)
{
    __shared__ float vmean_s[C8];
    __shared__ float attn_s[C8][C8 + 1];
    const int b = blockIdx.x;
    const int t = threadIdx.x;  // 0..63

    const float* xs = g_xsum + b*CC;
    float acc = 0.f;
    for (int c = 0; c < CC; ++c) acc += wv[t*CC + c] * xs[c];
    vmean_s[t] = acc * (1.f / NPIX) + bv[t];

    const float* Lg = g_logits + b*C8*C8;
    float col[C8];
    float m = -1e30f;
    #pragma unroll
    for (int o = 0; o < C8; ++o) { col[o] = Lg[o*C8 + t]; m = fmaxf(m, col[o]); }
    float s = 0.f;
    #pragma unroll
    for (int o = 0; o < C8; ++o) { col[o] = expf(col[o] - m); s += col[o]; }
    float inv = 1.f / s;
    #pragma unroll
    for (int o = 0; o < C8; ++o) attn_s[o][t] = col[o] * inv;
    __syncthreads();

    float r = 0.f;
    #pragma unroll
    for (int p = 0; p < C8; ++p) r += attn_s[t][p] * vmean_s[p];
    out[b*C8 + t] = r;
}

// -------------------------------------------------------------------------
extern "C" void kernel_launch(void* const* d_in, const int* in_sizes, int n_in,
                              void* d_out, int out_size) {
    const float* x  = (const float*)d_in[0];
    const float* wq = (const float*)d_in[1];
    const float* bq = (const float*)d_in[2];
    const float* wk = (const float*)d_in[3];
    const float* bk = (const float*)d_in[4];
    const float* wv = (const float*)d_in[5];
    const float* bv = (const float*)d_in[6];
    float* out = (float*)d_out;

    cudaFuncSetAttribute(qk_kernel,
                         cudaFuncAttributeMaxDynamicSharedMemorySize, SMEM_BYTES);

    prep_kernel<<<256, 256>>>(wq, wk);
    qk_kernel<<<296, 256, SMEM_BYTES>>>(x, bq, bk);
    finalize_kernel<<<BB, C8>>>(wv, bv, out);
}

// round 9
// speedup vs baseline: 1.4365x; 1.3731x over previous
#include <cuda_runtime.h>
#include <cuda_fp16.h>

#define BB 32
#define CC 512
#define C8 64
#define NPIX 4096
#define NT 128
#define CT 64
#define CTILES 8
#define NITEMS (BB*(NPIX/NT))   // 1024

#define ROWB 144                 // padded row stride (bytes): conflict-free ldmatrix
#define PLANE (128*ROWB)         // 18432 B per fp16 plane tile
#define SM_W 0                   // 2 planes of W   [p][m=128][k=64(+pad)]
#define SM_X (2*PLANE)           // 2 planes of X   [p][n=128][k=64(+pad)]
#define SMEM_BYTES (4*PLANE)     // 73728

typedef unsigned u32;
typedef unsigned long long u64t;
typedef unsigned short u16t;

// ---------------- helpers ----------------
__device__ __forceinline__ u32 smem_u32(const void* p) {
    u32 a; asm("{ .reg .u64 t; cvta.to.shared.u64 t, %1; cvt.u32.u64 %0, t; }" : "=r"(a) : "l"(p));
    return a;
}
__device__ __forceinline__ u64t pack2f(float lo, float hi) {
    u64t r; asm("mov.b64 %0, {%1, %2};" : "=l"(r) : "f"(lo), "f"(hi)); return r;
}
__device__ __forceinline__ u64t fma2(u64t a, u64t b, u64t c) {
    u64t d; asm("fma.rn.f32x2 %0, %1, %2, %3;" : "=l"(d) : "l"(a), "l"(b), "l"(c)); return d;
}
__device__ __forceinline__ void unpack2(u64t v, float& lo, float& hi) {
    asm("mov.b64 {%0, %1}, %2;" : "=f"(lo), "=f"(hi) : "l"(v));
}
__device__ __forceinline__ void ldsm4(u32* r, u32 addr) {
    asm volatile("ldmatrix.sync.aligned.m8n8.x4.shared.b16 {%0,%1,%2,%3}, [%4];"
        : "=r"(r[0]), "=r"(r[1]), "=r"(r[2]), "=r"(r[3]) : "r"(addr));
}
__device__ __forceinline__ void ldsm2(u32* r, u32 addr) {
    asm volatile("ldmatrix.sync.aligned.m8n8.x2.shared.b16 {%0,%1}, [%2];"
        : "=r"(r[0]), "=r"(r[1]) : "r"(addr));
}
__device__ __forceinline__ void mma_f16(float* d, const u32* a, const u32* b) {
    asm volatile("mma.sync.aligned.m16n8k16.row.col.f32.f16.f16.f32 "
        "{%0,%1,%2,%3}, {%4,%5,%6,%7}, {%8,%9}, {%0,%1,%2,%3};"
        : "+f"(d[0]), "+f"(d[1]), "+f"(d[2]), "+f"(d[3])
        : "r"(a[0]), "r"(a[1]), "r"(a[2]), "r"(a[3]), "r"(b[0]), "r"(b[1]));
}
__device__ __forceinline__ u32 h2u(__half2 h) { return *reinterpret_cast<u32*>(&h); }

// ---------------- globals (no allocation allowed) ----------------
__device__ float g_logits[BB*C8*C8];
__device__ float g_xsum[BB*CC];
__device__ uint4 g_w4[8*2304];   // per ct: [p=2][m=128][72 halves] fp16 limbs
__device__ unsigned g_ctr;

// -------------------------------------------------------------------------
__global__ void prep_kernel(const float* __restrict__ wq,
                            const float* __restrict__ wk) {
    int t = blockIdx.x * blockDim.x + threadIdx.x;
    int S = gridDim.x * blockDim.x;
    if (t == 0) g_ctr = 0;
    for (int i = t; i < BB*C8*C8; i += S) g_logits[i] = 0.f;
    for (int i = t; i < BB*CC;    i += S) g_xsum[i]   = 0.f;
    u16t* wh = (u16t*)g_w4;
    const int total = 8*2*128*72;
    for (int i = t; i < total; i += S) {
        int kk = i % 72;
        int m  = (i / 72) & 127;
        int p  = (i / (72*128)) & 1;
        int ct = i / (72*128*2);
        u16t hv = 0;
        if (kk < 64) {
            int c = ct*64 + kk;
            float v = (m < 64) ? wq[m*CC + c] : wk[(m-64)*CC + c];
            __half f0 = __float2half_rn(v);
            if (p == 0) {
                hv = *reinterpret_cast<u16t*>(&f0);
            } else {
                __half f1 = __float2half_rn(v - __half2float(f0));
                hv = *reinterpret_cast<u16t*>(&f1);
            }
        }
        wh[i] = hv;
    }
}

// -------------------------------------------------------------------------
// Persistent kernel. Item = (batch, 128-px tile).
//  per k-chunk: copy W fp16-limb planes (L2), convert x->2 fp16 planes [n][k],
//  ldmatrix + mma.sync f16 (3 split combos {00,01,10}, fp32 accum).
//  Then q,k -> smem, FFMA2 logits, atomic flush.
// -------------------------------------------------------------------------
__global__ void __launch_bounds__(256, 2)
qk_kernel(const float* __restrict__ x,
          const float* __restrict__ bq,
          const float* __restrict__ bk)
{
    extern __shared__ char smem[];
    const u32 smem_base = smem_u32(smem);
    float* q_s = (float*)smem;           // [64][130] fp32 (post-mma alias)
    float* k_s = (float*)smem + 8320;
    __shared__ unsigned item_s;

    const int tid  = threadIdx.x;
    const int lane = tid & 31;
    const int wid  = tid >> 5;
    const int wm = wid & 3;              // M slice: m in [32*wm, 32*wm+32)
    const int wn = wid >> 2;             // N slice: n in [64*wn, 64*wn+64)
    const int mbase = wm*32, nbase = wn*64;

    // ldmatrix per-lane byte offsets (invariant)
    u32 offA[2], offB[8];
    #pragma unroll
    for (int mt = 0; mt < 2; mt++)
        offA[mt] = (u32)((mbase + mt*16 + (lane & 15))*ROWB + (lane >> 4)*16);
    #pragma unroll
    for (int nt = 0; nt < 8; nt++)
        offB[nt] = (u32)((nbase + nt*8 + (lane & 7))*ROWB + ((lane >> 3) & 1)*16);

    // bias for the q/k rows this thread writes
    const float* bsrc = (wm < 2) ? bq : bk;
    const int rq = lane >> 2;
    float bias0[2], bias1[2];
    #pragma unroll
    for (int mt = 0; mt < 2; mt++) {
        int r = (mbase & 63) + mt*16 + rq;
        bias0[mt] = bsrc[r];
        bias1[mt] = bsrc[r + 8];
    }

    const int cw = wid * 8;              // convert: 8 channels owned by this warp
    const int tx = tid & 15, ty = tid >> 4;
    const int o0 = ty * 4, p0 = tx * 4;  // logits tile

    while (true) {
        if (tid == 0) item_s = atomicAdd(&g_ctr, 1u);
        __syncthreads();
        const unsigned item = item_s;
        if (item >= NITEMS) break;
        const int b = item >> 5;
        const int n0g = (int)(item & 31) * NT;

        float acc[2][8][4];
        #pragma unroll
        for (int mt = 0; mt < 2; mt++)
            #pragma unroll
            for (int nt = 0; nt < 8; nt++)
                #pragma unroll
                for (int r = 0; r < 4; r++) acc[mt][nt][r] = 0.f;

        for (int ct = 0; ct < CTILES; ++ct) {
            __syncthreads();  // prior-phase smem reads complete

            // ---- copy W fp16 planes for this chunk (L2-resident) ----
            {
                const uint4* src = g_w4 + ct*2304;
                uint4* dW = (uint4*)(smem + SM_W);
                for (int i = tid; i < 2304; i += 256) dW[i] = src[i];
            }

            // ---- convert x[64c x 128n] -> 2 fp16 planes [n][k=c] ----
            float csum[8];
            #pragma unroll
            for (int j = 0; j < 8; j++) csum[j] = 0.f;
            const float* xb = x + ((size_t)b*CC + (size_t)(ct*CT + cw))*NPIX + n0g;
            #pragma unroll
            for (int ni = 0; ni < 4; ni++) {
                const int n = ni*32 + lane;
                float v[8];
                #pragma unroll
                for (int j = 0; j < 8; j++) {
                    v[j] = xb[(size_t)j*NPIX + n];
                    csum[j] += v[j];
                }
                __half2 a0 = __floats2half2_rn(v[0], v[1]);
                __half2 a1 = __floats2half2_rn(v[2], v[3]);
                __half2 a2 = __floats2half2_rn(v[4], v[5]);
                __half2 a3 = __floats2half2_rn(v[6], v[7]);
                __half2 b0 = __floats2half2_rn(v[0] - __low2float(a0), v[1] - __high2float(a0));
                __half2 b1 = __floats2half2_rn(v[2] - __low2float(a1), v[3] - __high2float(a1));
                __half2 b2 = __floats2half2_rn(v[4] - __low2float(a2), v[5] - __high2float(a2));
                __half2 b3 = __floats2half2_rn(v[6] - __low2float(a3), v[7] - __high2float(a3));
                char* dst = smem + SM_X + n*ROWB + cw*2;
                *(uint4*)(dst)         = make_uint4(h2u(a0), h2u(a1), h2u(a2), h2u(a3));
                *(uint4*)(dst + PLANE) = make_uint4(h2u(b0), h2u(b1), h2u(b2), h2u(b3));
            }
            #pragma unroll
            for (int j = 0; j < 8; j++) {
                float s = csum[j];
                s += __shfl_xor_sync(0xffffffffu, s, 16);
                s += __shfl_xor_sync(0xffffffffu, s, 8);
                s += __shfl_xor_sync(0xffffffffu, s, 4);
                s += __shfl_xor_sync(0xffffffffu, s, 2);
                s += __shfl_xor_sync(0xffffffffu, s, 1);
                if (lane == 0) atomicAdd(&g_xsum[b*CC + ct*CT + cw + j], s);
            }
            __syncthreads();

            // ---- tensor phase: 3 combos x 4 k-steps x (2m x 8n) mma ----
            const int pa[3] = {0,0,1};
            const int pb[3] = {0,1,0};
            #pragma unroll
            for (int cb = 0; cb < 3; cb++) {
                const u32 baseA = smem_base + SM_W + pa[cb]*PLANE;
                const u32 baseB = smem_base + SM_X + pb[cb]*PLANE;
                #pragma unroll
                for (int ks = 0; ks < 4; ks++) {
                    u32 a[2][4];
                    ldsm4(a[0], baseA + offA[0] + ks*32);
                    ldsm4(a[1], baseA + offA[1] + ks*32);
                    u32 bf[8][2];
                    #pragma unroll
                    for (int nt = 0; nt < 8; nt++)
                        ldsm2(bf[nt], baseB + offB[nt] + ks*32);
                    #pragma unroll
                    for (int mt = 0; mt < 2; mt++)
                        #pragma unroll
                        for (int nt = 0; nt < 8; nt++)
                            mma_f16(acc[mt][nt], a[mt], bf[nt]);
                }
            }
        }
        __syncthreads();  // all mma smem reads done; alias q_s/k_s

        // ---- q,k (+bias) -> smem [row][n] stride 130 ----
        {
            float* dst = (wm < 2) ? q_s : k_s;
            #pragma unroll
            for (int mt = 0; mt < 2; mt++) {
                const int r0 = (mbase & 63) + mt*16 + rq;
                #pragma unroll
                for (int nt = 0; nt < 8; nt++) {
                    const int col = nbase + nt*8 + (lane & 3)*2;
                    *(u64t*)&dst[r0*130 + col] =
                        pack2f(acc[mt][nt][0] + bias0[mt], acc[mt][nt][1] + bias0[mt]);
                    *(u64t*)&dst[(r0+8)*130 + col] =
                        pack2f(acc[mt][nt][2] + bias1[mt], acc[mt][nt][3] + bias1[mt]);
                }
            }
        }
        __syncthreads();

        // ---- logits += q @ k^T (packed f32x2 along n) ----
        u64t lacc[4][4];
        #pragma unroll
        for (int i = 0; i < 4; i++)
            #pragma unroll
            for (int j = 0; j < 4; j++) lacc[i][j] = 0ull;

        #pragma unroll 4
        for (int np = 0; np < NT/2; ++np) {
            u64t q2[4], k2[4];
            #pragma unroll
            for (int i = 0; i < 4; i++) q2[i] = *(const u64t*)&q_s[(o0+i)*130 + 2*np];
            #pragma unroll
            for (int j = 0; j < 4; j++) k2[j] = *(const u64t*)&k_s[(p0+j)*130 + 2*np];
            #pragma unroll
            for (int i = 0; i < 4; i++)
                #pragma unroll
                for (int j = 0; j < 4; j++)
                    lacc[i][j] = fma2(q2[i], k2[j], lacc[i][j]);
        }
        float* Lg = g_logits + b*C8*C8;
        #pragma unroll
        for (int i = 0; i < 4; i++)
            #pragma unroll
            for (int j = 0; j < 4; j++) {
                float lo, hi; unpack2(lacc[i][j], lo, hi);
                atomicAdd(&Lg[(o0+i)*C8 + p0 + j], lo + hi);
            }
        // loop-top __syncthreads guards smem reuse for next item
    }
}

// -------------------------------------------------------------------------
__global__ void finalize_kernel(const float* __restrict__ wv,
                                const float* __restrict__ bv,
                                float* __restrict__ out)
{
    __shared__ float vmean_s[C8];
    __shared__ float attn_s[C8][C8 + 1];
    const int b = blockIdx.x;
    const int t = threadIdx.x;  // 0..63

    const float* xs = g_xsum + b*CC;
    float acc = 0.f;
    for (int c = 0; c < CC; ++c) acc += wv[t*CC + c] * xs[c];
    vmean_s[t] = acc * (1.f / NPIX) + bv[t];

    const float* Lg = g_logits + b*C8*C8;
    float col[C8];
    float m = -1e30f;
    #pragma unroll
    for (int o = 0; o < C8; ++o) { col[o] = Lg[o*C8 + t]; m = fmaxf(m, col[o]); }
    float s = 0.f;
    #pragma unroll
    for (int o = 0; o < C8; ++o) { col[o] = expf(col[o] - m); s += col[o]; }
    float inv = 1.f / s;
    #pragma unroll
    for (int o = 0; o < C8; ++o) attn_s[o][t] = col[o] * inv;
    __syncthreads();

    float r = 0.f;
    #pragma unroll
    for (int p = 0; p < C8; ++p) r += attn_s[t][p] * vmean_s[p];
    out[b*C8 + t] = r;
}

// -------------------------------------------------------------------------
extern "C" void kernel_launch(void* const* d_in, const int* in_sizes, int n_in,
                              void* d_out, int out_size) {
    const float* x  = (const float*)d_in[0];
    const float* wq = (const float*)d_in[1];
    const float* bq = (const float*)d_in[2];
    const float* wk = (const float*)d_in[3];
    const float* bk = (const float*)d_in[4];
    const float* wv = (const float*)d_in[5];
    const float* bv = (const float*)d_in[6];
    float* out = (float*)d_out;

    cudaFuncSetAttribute(qk_kernel,
                         cudaFuncAttributeMaxDynamicSharedMemorySize, SMEM_BYTES);

    prep_kernel<<<256, 256>>>(wq, wk);
    qk_kernel<<<296, 256, SMEM_BYTES>>>(x, bq, bk);
    finalize_kernel<<<BB, C8>>>(wv, bv, out);
}

// round 10
// speedup vs baseline: 1.7716x; 1.2332x over previous
#include <cuda_runtime.h>
#include <cuda_fp16.h>

#define BB 32
#define CC 512
#define C8 64
#define NPIX 4096
#define NT 128
#define CT 64
#define CTILES 8
#define NITEMS (BB*(NPIX/NT))   // 1024

#define ROWB 144                 // padded row stride (bytes): conflict-free ldmatrix
#define PLANE (128*ROWB)         // 18432 B per fp16 plane tile
#define SM_W  0                  // W: 2 planes (36864 B), single buffer
#define SM_X0 36864              // X buffer 0: 2 planes
#define SM_X1 73728              // X buffer 1: 2 planes
#define SMEM_BYTES 110592

typedef unsigned u32;
typedef unsigned long long u64t;
typedef unsigned short u16t;

// ---------------- helpers ----------------
__device__ __forceinline__ u32 smem_u32(const void* p) {
    u32 a; asm("{ .reg .u64 t; cvta.to.shared.u64 t, %1; cvt.u32.u64 %0, t; }" : "=r"(a) : "l"(p));
    return a;
}
__device__ __forceinline__ u64t pack2f(float lo, float hi) {
    u64t r; asm("mov.b64 %0, {%1, %2};" : "=l"(r) : "f"(lo), "f"(hi)); return r;
}
__device__ __forceinline__ u64t fma2(u64t a, u64t b, u64t c) {
    u64t d; asm("fma.rn.f32x2 %0, %1, %2, %3;" : "=l"(d) : "l"(a), "l"(b), "l"(c)); return d;
}
__device__ __forceinline__ void unpack2(u64t v, float& lo, float& hi) {
    asm("mov.b64 {%0, %1}, %2;" : "=f"(lo), "=f"(hi) : "l"(v));
}
__device__ __forceinline__ void ldsm4(u32* r, u32 addr) {
    asm volatile("ldmatrix.sync.aligned.m8n8.x4.shared.b16 {%0,%1,%2,%3}, [%4];"
        : "=r"(r[0]), "=r"(r[1]), "=r"(r[2]), "=r"(r[3]) : "r"(addr));
}
__device__ __forceinline__ void ldsm2(u32* r, u32 addr) {
    asm volatile("ldmatrix.sync.aligned.m8n8.x2.shared.b16 {%0,%1}, [%2];"
        : "=r"(r[0]), "=r"(r[1]) : "r"(addr));
}
__device__ __forceinline__ void mma_f16(float* d, const u32* a, const u32* b) {
    asm volatile("mma.sync.aligned.m16n8k16.row.col.f32.f16.f16.f32 "
        "{%0,%1,%2,%3}, {%4,%5,%6,%7}, {%8,%9}, {%0,%1,%2,%3};"
        : "+f"(d[0]), "+f"(d[1]), "+f"(d[2]), "+f"(d[3])
        : "r"(a[0]), "r"(a[1]), "r"(a[2]), "r"(a[3]), "r"(b[0]), "r"(b[1]));
}
__device__ __forceinline__ u32 h2u(__half2 h) { return *reinterpret_cast<u32*>(&h); }

// one combo-block: 4 k-steps x (2m x 8n) MMAs against one (Wplane, Xplane) pair
__device__ __forceinline__ void mma_cb(float acc[2][8][4], u32 baseA, u32 baseB,
                                       const u32* offA, const u32* offB) {
    #pragma unroll
    for (int ks = 0; ks < 4; ks++) {
        u32 a[2][4];
        ldsm4(a[0], baseA + offA[0] + ks*32);
        ldsm4(a[1], baseA + offA[1] + ks*32);
        u32 bf[8][2];
        #pragma unroll
        for (int nt = 0; nt < 8; nt++)
            ldsm2(bf[nt], baseB + offB[nt] + ks*32);
        #pragma unroll
        for (int mt = 0; mt < 2; mt++)
            #pragma unroll
            for (int nt = 0; nt < 8; nt++)
                mma_f16(acc[mt][nt], a[mt], bf[nt]);
    }
}

// convert pipeline pieces: each group = 1 pixel column slice (n = g*32+lane), 8 channels
__device__ __forceinline__ void ldg_grp(float* v, const float* xb, int g, int lane) {
    const int n = g*32 + lane;
    #pragma unroll
    for (int j = 0; j < 8; j++) v[j] = xb[(size_t)j*NPIX + n];
}
__device__ __forceinline__ void proc_grp(const float* v, char* xdst, int g, int lane,
                                         int cw, float* csum) {
    const int n = g*32 + lane;
    #pragma unroll
    for (int j = 0; j < 8; j++) csum[j] += v[j];
    __half2 a0 = __floats2half2_rn(v[0], v[1]);
    __half2 a1 = __floats2half2_rn(v[2], v[3]);
    __half2 a2 = __floats2half2_rn(v[4], v[5]);
    __half2 a3 = __floats2half2_rn(v[6], v[7]);
    __half2 b0 = __floats2half2_rn(v[0] - __low2float(a0), v[1] - __high2float(a0));
    __half2 b1 = __floats2half2_rn(v[2] - __low2float(a1), v[3] - __high2float(a1));
    __half2 b2 = __floats2half2_rn(v[4] - __low2float(a2), v[5] - __high2float(a2));
    __half2 b3 = __floats2half2_rn(v[6] - __low2float(a3), v[7] - __high2float(a3));
    char* dst = xdst + n*ROWB + cw*2;
    *(uint4*)(dst)         = make_uint4(h2u(a0), h2u(a1), h2u(a2), h2u(a3));
    *(uint4*)(dst + PLANE) = make_uint4(h2u(b0), h2u(b1), h2u(b2), h2u(b3));
}
__device__ __forceinline__ void flush_csum(float* csum, float* gx, int lane) {
    #pragma unroll
    for (int j = 0; j < 8; j++) {
        float s = csum[j];
        s += __shfl_xor_sync(0xffffffffu, s, 16);
        s += __shfl_xor_sync(0xffffffffu, s, 8);
        s += __shfl_xor_sync(0xffffffffu, s, 4);
        s += __shfl_xor_sync(0xffffffffu, s, 2);
        s += __shfl_xor_sync(0xffffffffu, s, 1);
        if (lane == 0) atomicAdd(&gx[j], s);
    }
}

// ---------------- globals (no allocation allowed) ----------------
__device__ float g_logits[BB*C8*C8];
__device__ float g_xsum[BB*CC];
__device__ uint4 g_w4[8*2304];   // per ct: [p=2][m=128][72 halves] fp16 limbs
__device__ unsigned g_ctr;

// -------------------------------------------------------------------------
__global__ void prep_kernel(const float* __restrict__ wq,
                            const float* __restrict__ wk) {
    int t = blockIdx.x * blockDim.x + threadIdx.x;
    int S = gridDim.x * blockDim.x;
    if (t == 0) g_ctr = 0;
    for (int i = t; i < BB*C8*C8; i += S) g_logits[i] = 0.f;
    for (int i = t; i < BB*CC;    i += S) g_xsum[i]   = 0.f;
    u16t* wh = (u16t*)g_w4;
    const int total = 8*2*128*72;
    for (int i = t; i < total; i += S) {
        int kk = i % 72;
        int m  = (i / 72) & 127;
        int p  = (i / (72*128)) & 1;
        int ct = i / (72*128*2);
        u16t hv = 0;
        if (kk < 64) {
            int c = ct*64 + kk;
            float v = (m < 64) ? wq[m*CC + c] : wk[(m-64)*CC + c];
            __half f0 = __float2half_rn(v);
            if (p == 0) {
                hv = *reinterpret_cast<u16t*>(&f0);
            } else {
                __half f1 = __float2half_rn(v - __half2float(f0));
                hv = *reinterpret_cast<u16t*>(&f1);
            }
        }
        wh[i] = hv;
    }
}

// -------------------------------------------------------------------------
// Persistent kernel, software-pipelined: converts for chunk ct+1 are issued
// interleaved with the MMA combo-blocks of chunk ct (X double-buffered), so
// LSU/FMA work fills the issue slots the tensor pipe's back-pressure leaves.
// -------------------------------------------------------------------------
__global__ void __launch_bounds__(256, 2)
qk_kernel(const float* __restrict__ x,
          const float* __restrict__ bq,
          const float* __restrict__ bk)
{
    extern __shared__ char smem[];
    const u32 smem_base = smem_u32(smem);
    float* q_s = (float*)smem;           // [64][130] fp32 (post-mma alias)
    float* k_s = (float*)smem + 8320;
    __shared__ unsigned item_s;

    const int tid  = threadIdx.x;
    const int lane = tid & 31;
    const int wid  = tid >> 5;
    const int wm = wid & 3;              // M slice: m in [32*wm, 32*wm+32)
    const int wn = wid >> 2;             // N slice: n in [64*wn, 64*wn+64)
    const int mbase = wm*32, nbase = wn*64;

    // ldmatrix per-lane byte offsets (plane-relative, invariant)
    u32 offA[2], offB[8];
    #pragma unroll
    for (int mt = 0; mt < 2; mt++)
        offA[mt] = (u32)((mbase + mt*16 + (lane & 15))*ROWB + (lane >> 4)*16);
    #pragma unroll
    for (int nt = 0; nt < 8; nt++)
        offB[nt] = (u32)((nbase + nt*8 + (lane & 7))*ROWB + ((lane >> 3) & 1)*16);

    // bias for the q/k rows this thread writes
    const float* bsrc = (wm < 2) ? bq : bk;
    const int rq = lane >> 2;
    float bias0[2], bias1[2];
    #pragma unroll
    for (int mt = 0; mt < 2; mt++) {
        int r = (mbase & 63) + mt*16 + rq;
        bias0[mt] = bsrc[r];
        bias1[mt] = bsrc[r + 8];
    }

    const int cw = wid * 8;              // convert: 8 channels owned by this warp
    const int tx = tid & 15, ty = tid >> 4;
    const int o0 = ty * 4, p0 = tx * 4;  // logits tile

    while (true) {
        if (tid == 0) item_s = atomicAdd(&g_ctr, 1u);
        __syncthreads();                 // also: logits reads done before new writes
        const unsigned item = item_s;
        if (item >= NITEMS) break;
        const int b = item >> 5;
        const int n0g = (int)(item & 31) * NT;

        float acc[2][8][4];
        #pragma unroll
        for (int mt = 0; mt < 2; mt++)
            #pragma unroll
            for (int nt = 0; nt < 8; nt++)
                #pragma unroll
                for (int r = 0; r < 4; r++) acc[mt][nt][r] = 0.f;

        // ---- prologue: W(0) copy + convert chunk 0 -> X0 ----
        {
            const uint4* src = g_w4;
            uint4* dW = (uint4*)(smem + SM_W);
            for (int i = tid; i < 2304; i += 256) dW[i] = src[i];

            const float* xb0 = x + ((size_t)b*CC + (size_t)cw)*NPIX + n0g;
            char* x0p = smem + SM_X0;
            float csum[8] = {0,0,0,0,0,0,0,0};
            float va[8], vb[8];
            ldg_grp(va, xb0, 0, lane);
            ldg_grp(vb, xb0, 1, lane);
            proc_grp(va, x0p, 0, lane, cw, csum);
            ldg_grp(va, xb0, 2, lane);
            proc_grp(vb, x0p, 1, lane, cw, csum);
            ldg_grp(vb, xb0, 3, lane);
            proc_grp(va, x0p, 2, lane, cw, csum);
            proc_grp(vb, x0p, 3, lane, cw, csum);
            flush_csum(csum, &g_xsum[b*CC + cw], lane);
        }
        __syncthreads();

        // ---- main pipelined loop over channel chunks ----
        for (int ct = 0; ct < CTILES; ++ct) {
            const bool more = (ct < CTILES-1);
            const u32 xcur = smem_base + ((ct & 1) ? SM_X1 : SM_X0);
            char* xnxt = smem + ((ct & 1) ? SM_X0 : SM_X1);
            const int ctn = more ? (ct + 1) : 0;   // safe index when !more
            const float* xbn = x + ((size_t)b*CC + (size_t)(ctn*CT + cw))*NPIX + n0g;
            const u32 aW = smem_base + SM_W;

            float csum[8] = {0,0,0,0,0,0,0,0};
            float va[8], vb[8];
            if (more) ldg_grp(va, xbn, 0, lane);

            // combo a0*x0
            mma_cb(acc, aW, xcur, offA, offB);
            if (more) { proc_grp(va, xnxt, 0, lane, cw, csum); ldg_grp(vb, xbn, 1, lane); }
            // combo a0*x1
            mma_cb(acc, aW, xcur + PLANE, offA, offB);
            if (more) { proc_grp(vb, xnxt, 1, lane, cw, csum); ldg_grp(va, xbn, 2, lane); }
            // combo a1*x0
            mma_cb(acc, aW + PLANE, xcur, offA, offB);
            if (more) {
                proc_grp(va, xnxt, 2, lane, cw, csum);
                ldg_grp(vb, xbn, 3, lane);
                proc_grp(vb, xnxt, 3, lane, cw, csum);
                flush_csum(csum, &g_xsum[b*CC + ctn*CT + cw], lane);
            }
            __syncthreads();   // MMA(ct) smem reads done; X(ct+1) visible
            if (more) {
                const uint4* src = g_w4 + (size_t)(ct+1)*2304;
                uint4* dW = (uint4*)(smem + SM_W);
                for (int i = tid; i < 2304; i += 256) dW[i] = src[i];
                __syncthreads();   // W(ct+1) visible before its MMAs
            }
        }

        // ---- q,k (+bias) -> smem [row][n] stride 130 ----
        {
            float* dst = (wm < 2) ? q_s : k_s;
            #pragma unroll
            for (int mt = 0; mt < 2; mt++) {
                const int r0 = (mbase & 63) + mt*16 + rq;
                #pragma unroll
                for (int nt = 0; nt < 8; nt++) {
                    const int col = nbase + nt*8 + (lane & 3)*2;
                    *(u64t*)&dst[r0*130 + col] =
                        pack2f(acc[mt][nt][0] + bias0[mt], acc[mt][nt][1] + bias0[mt]);
                    *(u64t*)&dst[(r0+8)*130 + col] =
                        pack2f(acc[mt][nt][2] + bias1[mt], acc[mt][nt][3] + bias1[mt]);
                }
            }
        }
        __syncthreads();

        // ---- logits += q @ k^T (packed f32x2 along n) ----
        u64t lacc[4][4];
        #pragma unroll
        for (int i = 0; i < 4; i++)
            #pragma unroll
            for (int j = 0; j < 4; j++) lacc[i][j] = 0ull;

        #pragma unroll 4
        for (int np = 0; np < NT/2; ++np) {
            u64t q2[4], k2[4];
            #pragma unroll
            for (int i = 0; i < 4; i++) q2[i] = *(const u64t*)&q_s[(o0+i)*130 + 2*np];
            #pragma unroll
            for (int j = 0; j < 4; j++) k2[j] = *(const u64t*)&k_s[(p0+j)*130 + 2*np];
            #pragma unroll
            for (int i = 0; i < 4; i++)
                #pragma unroll
                for (int j = 0; j < 4; j++)
                    lacc[i][j] = fma2(q2[i], k2[j], lacc[i][j]);
        }
        float* Lg = g_logits + b*C8*C8;
        #pragma unroll
        for (int i = 0; i < 4; i++)
            #pragma unroll
            for (int j = 0; j < 4; j++) {
                float lo, hi; unpack2(lacc[i][j], lo, hi);
                atomicAdd(&Lg[(o0+i)*C8 + p0 + j], lo + hi);
            }
        // loop-top __syncthreads guards smem reuse for next item
    }
}

// -------------------------------------------------------------------------
__global__ void finalize_kernel(const float* __restrict__ wv,
                                const float* __restrict__ bv,
                                float* __restrict__ out)
{
    __shared__ float vmean_s[C8];
    __shared__ float attn_s[C8][C8 + 1];
    const int b = blockIdx.x;
    const int t = threadIdx.x;  // 0..63

    const float* xs = g_xsum + b*CC;
    float acc = 0.f;
    for (int c = 0; c < CC; ++c) acc += wv[t*CC + c] * xs[c];
    vmean_s[t] = acc * (1.f / NPIX) + bv[t];

    const float* Lg = g_logits + b*C8*C8;
    float col[C8];
    float m = -1e30f;
    #pragma unroll
    for (int o = 0; o < C8; ++o) { col[o] = Lg[o*C8 + t]; m = fmaxf(m, col[o]); }
    float s = 0.f;
    #pragma unroll
    for (int o = 0; o < C8; ++o) { col[o] = expf(col[o] - m); s += col[o]; }
    float inv = 1.f / s;
    #pragma unroll
    for (int o = 0; o < C8; ++o) attn_s[o][t] = col[o] * inv;
    __syncthreads();

    float r = 0.f;
    #pragma unroll
    for (int p = 0; p < C8; ++p) r += attn_s[t][p] * vmean_s[p];
    out[b*C8 + t] = r;
}

// -------------------------------------------------------------------------
extern "C" void kernel_launch(void* const* d_in, const int* in_sizes, int n_in,
                              void* d_out, int out_size) {
    const float* x  = (const float*)d_in[0];
    const float* wq = (const float*)d_in[1];
    const float* bq = (const float*)d_in[2];
    const float* wk = (const float*)d_in[3];
    const float* bk = (const float*)d_in[4];
    const float* wv = (const float*)d_in[5];
    const float* bv = (const float*)d_in[6];
    float* out = (float*)d_out;

    cudaFuncSetAttribute(qk_kernel,
                         cudaFuncAttributeMaxDynamicSharedMemorySize, SMEM_BYTES);

    prep_kernel<<<256, 256>>>(wq, wk);
    qk_kernel<<<296, 256, SMEM_BYTES>>>(x, bq, bk);
    finalize_kernel<<<BB, C8>>>(wv, bv, out);
}